// round 1
// baseline (speedup 1.0000x reference)
#include <cuda_runtime.h>

#define PI_F      3.14159265358979f
#define HALF_PI_F 1.57079632679490f

__global__ __launch_bounds__(256) void hqae_kernel(
    const float* __restrict__ x,  const float* __restrict__ qw,
    const float* __restrict__ W1, const float* __restrict__ b1,
    const float* __restrict__ W2, const float* __restrict__ b2,
    const float* __restrict__ W3, const float* __restrict__ b3,
    float* __restrict__ out, int n)
{
    // shared layout (floats): W1@0(64) b1@64(16) W2@80(512) b2@592(32)
    //                          W3@624(512) b3@1136(16) qw-trig@1152(16)
    __shared__ __align__(16) float sw[1168];
    const int tid = threadIdx.x;

    for (int i = tid; i < 64;  i += 256) sw[i]       = W1[i];
    for (int i = tid; i < 16;  i += 256) sw[64 + i]  = b1[i];
    for (int i = tid; i < 512; i += 256) sw[80 + i]  = W2[i];
    for (int i = tid; i < 32;  i += 256) sw[592 + i] = b2[i];
    for (int i = tid; i < 512; i += 256) sw[624 + i] = W3[i];
    for (int i = tid; i < 16;  i += 256) sw[1136 + i] = b3[i];
    if (tid < 4) {
        float s, c;
        __sincosf(qw[2 * tid] * 0.5f, &s, &c);   // RY half-angle
        sw[1152 + tid] = c; sw[1156 + tid] = s;
        __sincosf(qw[2 * tid + 1], &s, &c);      // RZ full angle (global-phase trick)
        sw[1160 + tid] = c; sw[1164 + tid] = s;
    }
    __syncthreads();

    const int b = blockIdx.x * 256 + tid;
    if (b >= n) return;

    // ---- load x row (4x LDG.128, all bytes used across warp) ----
    const float4* xv = (const float4*)(x + (size_t)b * 16);
    float4 x0 = xv[0], x1 = xv[1];
    float xa[8] = {x0.x, x0.y, x0.z, x0.w, x1.x, x1.y, x1.z, x1.w};

    // ---- layer 1: product state (global phase dropped) ----
    float vr[4][2], vi[4][2];
#pragma unroll
    for (int i = 0; i < 4; i++) {
        float s, c;  __sincosf(xa[i] * HALF_PI_F, &s, &c);
        float ps, pc; __sincosf(xa[i + 4] * PI_F, &ps, &pc);
        vr[i][0] = c;       vi[i][0] = 0.0f;
        vr[i][1] = s * pc;  vi[i][1] = s * ps;
    }
    float ar[16], ai[16];
    {
        float t2r[4], t2i[4];
#pragma unroll
        for (int i0 = 0; i0 < 2; i0++)
#pragma unroll
            for (int i1 = 0; i1 < 2; i1++) {
                int k = i0 * 2 + i1;
                t2r[k] = vr[0][i0] * vr[1][i1] - vi[0][i0] * vi[1][i1];
                t2i[k] = vr[0][i0] * vi[1][i1] + vi[0][i0] * vr[1][i1];
            }
        float t3r[8], t3i[8];
#pragma unroll
        for (int k = 0; k < 4; k++)
#pragma unroll
            for (int i2 = 0; i2 < 2; i2++) {
                int j = k * 2 + i2;
                t3r[j] = t2r[k] * vr[2][i2] - t2i[k] * vi[2][i2];
                t3i[j] = t2r[k] * vi[2][i2] + t2i[k] * vr[2][i2];
            }
#pragma unroll
        for (int k = 0; k < 8; k++)
#pragma unroll
            for (int i3 = 0; i3 < 2; i3++) {
                int j = k * 2 + i3;
                ar[j] = t3r[k] * vr[3][i3] - t3i[k] * vi[3][i3];
                ai[j] = t3r[k] * vi[3][i3] + t3i[k] * vr[3][i3];
            }
    }

    // ---- CNOT chains are register relabelings ----
#define SWAMP(p, q) { float t_ = ar[p]; ar[p] = ar[q]; ar[q] = t_; \
                      t_ = ai[p]; ai[p] = ai[q]; ai[q] = t_; }
    // CNOT(0,1), CNOT(1,2), CNOT(2,3)   [wire0 = bit value 8 (MSB)]
    SWAMP(8,12) SWAMP(9,13) SWAMP(10,14) SWAMP(11,15)
    SWAMP(4,6)  SWAMP(5,7)  SWAMP(12,14) SWAMP(13,15)
    SWAMP(2,3)  SWAMP(6,7)  SWAMP(10,11) SWAMP(14,15)

    // ---- variational layer: RY(qw[2i]) then RZ(qw[2i+1]) per qubit ----
#pragma unroll
    for (int i = 0; i < 4; i++) {
        const float c  = sw[1152 + i], s  = sw[1156 + i];
        const float zc = sw[1160 + i], zs = sw[1164 + i];
        const int m = 8 >> i;
#pragma unroll
        for (int k = 0; k < 16; k++) {
            if (k & m) continue;
            const int k1 = k | m;
            float a0r = ar[k],  a0i = ai[k];
            float a1r = ar[k1], a1i = ai[k1];
            float n1r = s * a0r + c * a1r, n1i = s * a0i + c * a1i;
            ar[k]  = c * a0r - s * a1r;   ai[k]  = c * a0i - s * a1i;
            // RZ: bit=1 amp gets e^{i*phi} (bit=0 phase dropped as global)
            ar[k1] = zc * n1r - zs * n1i; ai[k1] = zs * n1r + zc * n1i;
        }
    }

    // ---- second CNOT chain ----
    SWAMP(8,12) SWAMP(9,13) SWAMP(10,14) SWAMP(11,15)
    SWAMP(4,6)  SWAMP(5,7)  SWAMP(12,14) SWAMP(13,15)
    SWAMP(2,3)  SWAMP(6,7)  SWAMP(10,11) SWAMP(14,15)

    // ---- probs and PauliZ expvals ----
    float p[16];
#pragma unroll
    for (int k = 0; k < 16; k++) p[k] = ar[k] * ar[k] + ai[k] * ai[k];
    float z[4];
#pragma unroll
    for (int i = 0; i < 4; i++) {
        const int m = 8 >> i;
        float acc = 0.0f;
#pragma unroll
        for (int k = 0; k < 16; k++) acc += (k & m) ? -p[k] : p[k];
        z[i] = acc;
    }

    // ---- MLP decoder (weights in shared, LDS.128) ----
    const float4* sW1 = (const float4*)(sw);
    const float*  sb1 = sw + 64;
    const float4* sW2 = (const float4*)(sw + 80);
    const float*  sb2 = sw + 592;
    const float4* sW3 = (const float4*)(sw + 624);
    const float*  sb3 = sw + 1136;

    float h1[16];
#pragma unroll
    for (int j = 0; j < 16; j++) {
        float4 w = sW1[j];
        float a = sb1[j] + w.x * z[0] + w.y * z[1] + w.z * z[2] + w.w * z[3];
        h1[j] = fmaxf(a, 0.0f);
    }
    float h2[32];
#pragma unroll
    for (int j = 0; j < 32; j++) {
        float a = sb2[j];
#pragma unroll
        for (int q = 0; q < 4; q++) {
            float4 w = sW2[j * 4 + q];
            a += w.x * h1[q * 4] + w.y * h1[q * 4 + 1]
               + w.z * h1[q * 4 + 2] + w.w * h1[q * 4 + 3];
        }
        h2[j] = fmaxf(a, 0.0f);
    }
    float o[16];
#pragma unroll
    for (int j = 0; j < 16; j++) {
        float a = sb3[j];
#pragma unroll
        for (int q = 0; q < 8; q++) {
            float4 w = sW3[j * 8 + q];
            a += w.x * h2[q * 4] + w.y * h2[q * 4 + 1]
               + w.z * h2[q * 4 + 2] + w.w * h2[q * 4 + 3];
        }
        o[j] = a;
    }

    float4* ov = (float4*)(out + (size_t)b * 16);
    ov[0] = make_float4(o[0],  o[1],  o[2],  o[3]);
    ov[1] = make_float4(o[4],  o[5],  o[6],  o[7]);
    ov[2] = make_float4(o[8],  o[9],  o[10], o[11]);
    ov[3] = make_float4(o[12], o[13], o[14], o[15]);
}

extern "C" void kernel_launch(void* const* d_in, const int* in_sizes, int n_in,
                              void* d_out, int out_size)
{
    const float* x  = (const float*)d_in[0];
    const float* qw = (const float*)d_in[1];
    const float* W1 = (const float*)d_in[2];
    const float* b1 = (const float*)d_in[3];
    const float* W2 = (const float*)d_in[4];
    const float* b2 = (const float*)d_in[5];
    const float* W3 = (const float*)d_in[6];
    const float* b3 = (const float*)d_in[7];
    float* out = (float*)d_out;

    const int n = in_sizes[0] / 16;           // B
    const int blocks = (n + 255) / 256;
    hqae_kernel<<<blocks, 256>>>(x, qw, W1, b1, W2, b2, W3, b3, out, n);
}

// round 3
// speedup vs baseline: 1.1469x; 1.1469x over previous
#include <cuda_runtime.h>

#define PI_F      3.14159265358979f
#define HALF_PI_F 1.57079632679490f

typedef unsigned long long u64;
struct P { u64 v; };

__device__ __forceinline__ P mkP(u64 x){ P r; r.v = x; return r; }
__device__ __forceinline__ P pack2(float lo, float hi){
    P r; asm("mov.b64 %0,{%1,%2};" : "=l"(r.v) : "f"(lo), "f"(hi)); return r;
}
__device__ __forceinline__ void unpack2(P a, float& lo, float& hi){
    asm("mov.b64 {%0,%1},%2;" : "=f"(lo), "=f"(hi) : "l"(a.v));
}
__device__ __forceinline__ P mul2(P a, P b){
    P r; asm("mul.rn.f32x2 %0,%1,%2;" : "=l"(r.v) : "l"(a.v), "l"(b.v)); return r;
}
__device__ __forceinline__ P add2(P a, P b){
    P r; asm("add.rn.f32x2 %0,%1,%2;" : "=l"(r.v) : "l"(a.v), "l"(b.v)); return r;
}
__device__ __forceinline__ P fma2(P a, P b, P c){
    P r; asm("fma.rn.f32x2 %0,%1,%2,%3;" : "=l"(r.v) : "l"(a.v), "l"(b.v), "l"(c.v)); return r;
}
__device__ __forceinline__ P negP(P a){ P r; r.v = a.v ^ 0x8000000080000000ULL; return r; }
__device__ __forceinline__ P relu2(P a){
    float lo, hi; unpack2(a, lo, hi);
    return pack2(fmaxf(lo, 0.0f), fmaxf(hi, 0.0f));
}
// (ar+i*ai)*(br+i*bi) -> (rr, ri); NEG1 = packed {-1,-1}
__device__ __forceinline__ void cmul(P ar_, P ai_, P br_, P bi_, P& rr, P& ri, P NEG1){
    rr = fma2(mul2(ai_, bi_), NEG1, mul2(ar_, br_));
    ri = fma2(ar_, bi_, mul2(ai_, br_));
}

// shared layout in floats (all regions 16B-aligned), weights duplicated pairwise
#define OFF_W1   0      // 128
#define OFF_B1   128    // 32
#define OFF_W2   160    // 1024
#define OFF_B2   1184   // 64
#define OFF_W3   1248   // 1024
#define OFF_B3   2272   // 32
#define OFF_TRIG 2304   // 32
#define SW_TOTAL 2336

__global__ __launch_bounds__(256, 2) void hqae_kernel(
    const float* __restrict__ x,  const float* __restrict__ qw,
    const float* __restrict__ W1, const float* __restrict__ b1,
    const float* __restrict__ W2, const float* __restrict__ b2,
    const float* __restrict__ W3, const float* __restrict__ b3,
    float* __restrict__ out, int n)
{
    __shared__ __align__(16) float sw[SW_TOTAL];
    const int tid = threadIdx.x;

    // fill shared with pair-duplicated weights: {w0,w0,w1,w1,...}
    for (int i = tid; i < 64;  i += 256){ float w = W1[i]; sw[OFF_W1+2*i] = w; sw[OFF_W1+2*i+1] = w; }
    for (int i = tid; i < 16;  i += 256){ float w = b1[i]; sw[OFF_B1+2*i] = w; sw[OFF_B1+2*i+1] = w; }
    for (int i = tid; i < 512; i += 256){ float w = W2[i]; sw[OFF_W2+2*i] = w; sw[OFF_W2+2*i+1] = w; }
    for (int i = tid; i < 32;  i += 256){ float w = b2[i]; sw[OFF_B2+2*i] = w; sw[OFF_B2+2*i+1] = w; }
    for (int i = tid; i < 512; i += 256){ float w = W3[i]; sw[OFF_W3+2*i] = w; sw[OFF_W3+2*i+1] = w; }
    for (int i = tid; i < 16;  i += 256){ float w = b3[i]; sw[OFF_B3+2*i] = w; sw[OFF_B3+2*i+1] = w; }
    if (tid < 4) {
        float s, c;
        __sincosf(qw[2*tid] * 0.5f, &s, &c);   // RY half-angle
        sw[OFF_TRIG + tid*8 + 0] = c; sw[OFF_TRIG + tid*8 + 1] = c;
        sw[OFF_TRIG + tid*8 + 2] = s; sw[OFF_TRIG + tid*8 + 3] = s;
        __sincosf(qw[2*tid + 1], &s, &c);      // RZ full angle (global-phase trick)
        sw[OFF_TRIG + tid*8 + 4] = c; sw[OFF_TRIG + tid*8 + 5] = c;
        sw[OFF_TRIG + tid*8 + 6] = s; sw[OFF_TRIG + tid*8 + 7] = s;
    }
    __syncthreads();

    const int half = n >> 1;                   // pair (b, b+half)
    const int b0 = blockIdx.x * 256 + tid;
    if (b0 >= half) return;
    const int b1i = b0 + half;

    const P NEG1 = mkP(0xBF800000BF800000ULL);
    const P ZERO = mkP(0ULL);

    // ---- load x rows for both elements ----
    const float4* xv0 = (const float4*)(x + (size_t)b0  * 16);
    const float4* xv1 = (const float4*)(x + (size_t)b1i * 16);
    float4 a0 = xv0[0], a1 = xv0[1];
    float4 c0v = xv1[0], c1v = xv1[1];
    float xA[8] = {a0.x, a0.y, a0.z, a0.w, a1.x, a1.y, a1.z, a1.w};
    float xB[8] = {c0v.x, c0v.y, c0v.z, c0v.w, c1v.x, c1v.y, c1v.z, c1v.w};

    // ---- layer 1: per-qubit vectors (amp0 real = cq, amp1 complex = ur,ui) ----
    P cq[4], urq[4], uiq[4];
#pragma unroll
    for (int i = 0; i < 4; i++) {
        float sA, cA, sB, cB;
        __sincosf(xA[i] * HALF_PI_F, &sA, &cA);
        __sincosf(xB[i] * HALF_PI_F, &sB, &cB);
        float psA, pcA, psB, pcB;
        __sincosf(xA[i+4] * PI_F, &psA, &pcA);
        __sincosf(xB[i+4] * PI_F, &psB, &pcB);
        cq[i] = pack2(cA, cB);
        P s2  = pack2(sA, sB);
        urq[i] = mul2(s2, pack2(pcA, pcB));
        uiq[i] = mul2(s2, pack2(psA, psB));
    }

    // ---- tensor product, keeping the amp-0 real chain explicit ----
    P t2r[4], t2i[4];
    t2r[0] = mul2(cq[0], cq[1]);                         // real
    t2r[1] = mul2(cq[0], urq[1]); t2i[1] = mul2(cq[0], uiq[1]);
    t2r[2] = mul2(urq[0], cq[1]); t2i[2] = mul2(uiq[0], cq[1]);
    cmul(urq[0], uiq[0], urq[1], uiq[1], t2r[3], t2i[3], NEG1);

    P t3r[8], t3i[8];
    t3r[0] = mul2(t2r[0], cq[2]);                        // real
    t3r[1] = mul2(t2r[0], urq[2]); t3i[1] = mul2(t2r[0], uiq[2]);
#pragma unroll
    for (int k = 1; k < 4; k++) {
        t3r[2*k]   = mul2(t2r[k], cq[2]);
        t3i[2*k]   = mul2(t2i[k], cq[2]);
        cmul(t2r[k], t2i[k], urq[2], uiq[2], t3r[2*k+1], t3i[2*k+1], NEG1);
    }

    P ar[16], ai[16];
    ar[0] = mul2(t3r[0], cq[3]); ai[0] = ZERO;
    ar[1] = mul2(t3r[0], urq[3]); ai[1] = mul2(t3r[0], uiq[3]);
#pragma unroll
    for (int k = 1; k < 8; k++) {
        ar[2*k]   = mul2(t3r[k], cq[3]);
        ai[2*k]   = mul2(t3i[k], cq[3]);
        cmul(t3r[k], t3i[k], urq[3], uiq[3], ar[2*k+1], ai[2*k+1], NEG1);
    }

    // ---- CNOT chains: register relabelings (wire0 = bit value 8) ----
#define SWAMP(p, q) { P t_ = ar[p]; ar[p] = ar[q]; ar[q] = t_; \
                      t_ = ai[p]; ai[p] = ai[q]; ai[q] = t_; }
    SWAMP(8,12) SWAMP(9,13) SWAMP(10,14) SWAMP(11,15)
    SWAMP(4,6)  SWAMP(5,7)  SWAMP(12,14) SWAMP(13,15)
    SWAMP(2,3)  SWAMP(6,7)  SWAMP(10,11) SWAMP(14,15)

    // ---- variational layer: RY(qw[2i]) then RZ(qw[2i+1]) per qubit ----
    const ulonglong2* trp = (const ulonglong2*)(sw + OFF_TRIG);
#pragma unroll
    for (int i = 0; i < 4; i++) {
        ulonglong2 u0 = trp[i*2], u1 = trp[i*2+1];
        P cy = mkP(u0.x), sy = mkP(u0.y), zc = mkP(u1.x), zs = mkP(u1.y);
        P syn = negP(sy), zsn = negP(zs);
        const int m = 8 >> i;
#pragma unroll
        for (int k = 0; k < 16; k++) {
            if (k & m) continue;
            const int k1 = k | m;
            P a0r = ar[k],  a0i = ai[k];
            P a1r = ar[k1], a1i = ai[k1];
            P n1r = fma2(sy, a0r, mul2(cy, a1r));
            P n1i = fma2(sy, a0i, mul2(cy, a1i));
            ar[k]  = fma2(syn, a1r, mul2(cy, a0r));
            ai[k]  = fma2(syn, a1i, mul2(cy, a0i));
            ar[k1] = fma2(zsn, n1i, mul2(zc, n1r));
            ai[k1] = fma2(zs,  n1r, mul2(zc, n1i));
        }
    }

    // ---- second CNOT chain ----
    SWAMP(8,12) SWAMP(9,13) SWAMP(10,14) SWAMP(11,15)
    SWAMP(4,6)  SWAMP(5,7)  SWAMP(12,14) SWAMP(13,15)
    SWAMP(2,3)  SWAMP(6,7)  SWAMP(10,11) SWAMP(14,15)

    // ---- probs and PauliZ expvals ----
    P p[16];
#pragma unroll
    for (int k = 0; k < 16; k++) p[k] = fma2(ar[k], ar[k], mul2(ai[k], ai[k]));
    P z[4];
#pragma unroll
    for (int i = 0; i < 4; i++) {
        const int m = 8 >> i;
        P acc = p[0];
#pragma unroll
        for (int k = 1; k < 16; k++)
            acc = (k & m) ? fma2(p[k], NEG1, acc) : add2(acc, p[k]);
        z[i] = acc;
    }

    // ---- MLP decoder with pair-duplicated weights (each LDS.128 = 2 packed ops) ----
    const ulonglong2* W1p = (const ulonglong2*)(sw + OFF_W1);
    const P*          B1p = (const P*)(sw + OFF_B1);
    const ulonglong2* W2p = (const ulonglong2*)(sw + OFF_W2);
    const P*          B2p = (const P*)(sw + OFF_B2);
    const ulonglong2* W3p = (const ulonglong2*)(sw + OFF_W3);
    const P*          B3p = (const P*)(sw + OFF_B3);

    P h1[16];
#pragma unroll
    for (int j = 0; j < 16; j++) {
        ulonglong2 u0 = W1p[2*j], u1 = W1p[2*j+1];
        P acc = B1p[j];
        acc = fma2(mkP(u0.x), z[0], acc);
        acc = fma2(mkP(u0.y), z[1], acc);
        acc = fma2(mkP(u1.x), z[2], acc);
        acc = fma2(mkP(u1.y), z[3], acc);
        h1[j] = relu2(acc);
    }
    P h2[32];
#pragma unroll
    for (int j = 0; j < 32; j++) {
        P acc = B2p[j];
#pragma unroll
        for (int q = 0; q < 8; q++) {
            ulonglong2 u = W2p[j*8 + q];
            acc = fma2(mkP(u.x), h1[2*q],     acc);
            acc = fma2(mkP(u.y), h1[2*q + 1], acc);
        }
        h2[j] = relu2(acc);
    }

    float* o0 = out + (size_t)b0  * 16;
    float* o1 = out + (size_t)b1i * 16;
#pragma unroll
    for (int g = 0; g < 4; g++) {
        float ol[4], oh[4];
#pragma unroll
        for (int jj = 0; jj < 4; jj++) {
            const int j = g*4 + jj;
            P acc = B3p[j];
#pragma unroll
            for (int q = 0; q < 16; q++) {
                ulonglong2 u = W3p[j*16 + q];
                acc = fma2(mkP(u.x), h2[2*q],     acc);
                acc = fma2(mkP(u.y), h2[2*q + 1], acc);
            }
            unpack2(acc, ol[jj], oh[jj]);
        }
        ((float4*)o0)[g] = make_float4(ol[0], ol[1], ol[2], ol[3]);
        ((float4*)o1)[g] = make_float4(oh[0], oh[1], oh[2], oh[3]);
    }
}

extern "C" void kernel_launch(void* const* d_in, const int* in_sizes, int n_in,
                              void* d_out, int out_size)
{
    const float* x  = (const float*)d_in[0];
    const float* qw = (const float*)d_in[1];
    const float* W1 = (const float*)d_in[2];
    const float* b1 = (const float*)d_in[3];
    const float* W2 = (const float*)d_in[4];
    const float* b2 = (const float*)d_in[5];
    const float* W3 = (const float*)d_in[6];
    const float* b3 = (const float*)d_in[7];
    float* out = (float*)d_out;

    const int n = in_sizes[0] / 16;           // B (even)
    const int half = n >> 1;
    const int blocks = (half + 255) / 256;
    hqae_kernel<<<blocks, 256>>>(x, qw, W1, b1, W2, b2, W3, b3, out, n);
}

// round 4
// speedup vs baseline: 1.2602x; 1.0988x over previous
#include <cuda_runtime.h>

#define PI_F      3.14159265358979f
#define HALF_PI_F 1.57079632679490f

typedef unsigned long long u64;
struct P { u64 v; };

__device__ __forceinline__ P mkP(u64 x){ P r; r.v = x; return r; }
__device__ __forceinline__ P pack2(float lo, float hi){
    P r; asm("mov.b64 %0,{%1,%2};" : "=l"(r.v) : "f"(lo), "f"(hi)); return r;
}
__device__ __forceinline__ P dupP(float v){
    P r; asm("mov.b64 %0,{%1,%1};" : "=l"(r.v) : "f"(v)); return r;
}
__device__ __forceinline__ void unpack2(P a, float& lo, float& hi){
    asm("mov.b64 {%0,%1},%2;" : "=f"(lo), "=f"(hi) : "l"(a.v));
}
__device__ __forceinline__ P fma2(P a, P b, P c){
    P r; asm("fma.rn.f32x2 %0,%1,%2,%3;" : "=l"(r.v) : "l"(a.v), "l"(b.v), "l"(c.v)); return r;
}
__device__ __forceinline__ P negP(P a){ P r; r.v = a.v ^ 0x8000000080000000ULL; return r; }

#define K_ZERO (mkP(0ULL))
#define K_ONE  (mkP(0x3F8000003F800000ULL))
#define K_NEG1 (mkP(0xBF800000BF800000ULL))

// packed mul/add expressed as FFMA2 (the only packed fp32 SASS op)
__device__ __forceinline__ P mul2(P a, P b){ return fma2(a, b, K_ZERO); }
__device__ __forceinline__ P add2(P a, P b){ return fma2(a, K_ONE, b); }

// (ar+i*ai)*(br+i*bi) -> (rr, ri)
__device__ __forceinline__ void cmul(P ar_, P ai_, P br_, P bi_, P& rr, P& ri){
    rr = fma2(mul2(ai_, bi_), K_NEG1, mul2(ar_, br_));
    ri = fma2(ar_, bi_, mul2(ai_, br_));
}

// shared layout (floats). MLP weights TRANSPOSED, adjacent-neuron pairs, NOT duplicated.
// sW1[k*16 + j] = W1[j,k]   (k<4,  j<16)
// sW2[k*32 + j] = W2[j,k]   (k<16, j<32)
// sW3[k*16 + j] = W3[j,k]   (k<32, j<16)
#define OFF_W1   0      // 64
#define OFF_B1   64     // 16
#define OFF_W2   80     // 512
#define OFF_B2   592    // 32
#define OFF_W3   624    // 512
#define OFF_B3   1136   // 16
#define OFF_TRIG 1152   // 32 (pair-duplicated, batch-packed use)
#define SW_TOTAL 1184

__global__ __launch_bounds__(256, 2) void hqae_kernel(
    const float* __restrict__ x,  const float* __restrict__ qw,
    const float* __restrict__ W1, const float* __restrict__ b1,
    const float* __restrict__ W2, const float* __restrict__ b2,
    const float* __restrict__ W3, const float* __restrict__ b3,
    float* __restrict__ out, int n)
{
    __shared__ __align__(16) float sw[SW_TOTAL];
    const int tid = threadIdx.x;

    for (int i = tid; i < 64;  i += 256){ int k = i >> 4, j = i & 15; sw[OFF_W1 + i] = W1[j*4 + k]; }
    for (int i = tid; i < 512; i += 256){ int k = i >> 5, j = i & 31; sw[OFF_W2 + i] = W2[j*16 + k]; }
    for (int i = tid; i < 512; i += 256){ int k = i >> 4, j = i & 15; sw[OFF_W3 + i] = W3[j*32 + k]; }
    for (int i = tid; i < 16;  i += 256) sw[OFF_B1 + i] = b1[i];
    for (int i = tid; i < 32;  i += 256) sw[OFF_B2 + i] = b2[i];
    for (int i = tid; i < 16;  i += 256) sw[OFF_B3 + i] = b3[i];
    if (tid < 4) {
        float s, c;
        __sincosf(qw[2*tid] * 0.5f, &s, &c);   // RY half-angle
        sw[OFF_TRIG + tid*8 + 0] = c; sw[OFF_TRIG + tid*8 + 1] = c;
        sw[OFF_TRIG + tid*8 + 2] = s; sw[OFF_TRIG + tid*8 + 3] = s;
        __sincosf(qw[2*tid + 1], &s, &c);      // RZ full angle (global-phase trick)
        sw[OFF_TRIG + tid*8 + 4] = c; sw[OFF_TRIG + tid*8 + 5] = c;
        sw[OFF_TRIG + tid*8 + 6] = s; sw[OFF_TRIG + tid*8 + 7] = s;
    }
    __syncthreads();

    const int half = n >> 1;                   // pair (b, b+half)
    const int b0 = blockIdx.x * 256 + tid;
    if (b0 >= half) return;
    const int b1i = b0 + half;

    // ---- load x rows for both elements ----
    const float4* xv0 = (const float4*)(x + (size_t)b0  * 16);
    const float4* xv1 = (const float4*)(x + (size_t)b1i * 16);
    float4 a0 = xv0[0], a1 = xv0[1];
    float4 c0v = xv1[0], c1v = xv1[1];
    float xA[8] = {a0.x, a0.y, a0.z, a0.w, a1.x, a1.y, a1.z, a1.w};
    float xB[8] = {c0v.x, c0v.y, c0v.z, c0v.w, c1v.x, c1v.y, c1v.z, c1v.w};

    // ---- layer 1: per-qubit product vectors (amp0 real = cq, amp1 = ur+i*ui) ----
    P cq[4], urq[4], uiq[4];
#pragma unroll
    for (int i = 0; i < 4; i++) {
        float sA, cA, sB, cB;
        __sincosf(xA[i] * HALF_PI_F, &sA, &cA);
        __sincosf(xB[i] * HALF_PI_F, &sB, &cB);
        float psA, pcA, psB, pcB;
        __sincosf(xA[i+4] * PI_F, &psA, &pcA);
        __sincosf(xB[i+4] * PI_F, &psB, &pcB);
        cq[i] = pack2(cA, cB);
        P s2  = pack2(sA, sB);
        urq[i] = mul2(s2, pack2(pcA, pcB));
        uiq[i] = mul2(s2, pack2(psA, psB));
    }

    // ---- tensor product (amp-0 real chain explicit) ----
    P t2r[4], t2i[4];
    t2r[0] = mul2(cq[0], cq[1]);
    t2r[1] = mul2(cq[0], urq[1]); t2i[1] = mul2(cq[0], uiq[1]);
    t2r[2] = mul2(urq[0], cq[1]); t2i[2] = mul2(uiq[0], cq[1]);
    cmul(urq[0], uiq[0], urq[1], uiq[1], t2r[3], t2i[3]);

    P t3r[8], t3i[8];
    t3r[0] = mul2(t2r[0], cq[2]);
    t3r[1] = mul2(t2r[0], urq[2]); t3i[1] = mul2(t2r[0], uiq[2]);
#pragma unroll
    for (int k = 1; k < 4; k++) {
        t3r[2*k] = mul2(t2r[k], cq[2]);
        t3i[2*k] = mul2(t2i[k], cq[2]);
        cmul(t2r[k], t2i[k], urq[2], uiq[2], t3r[2*k+1], t3i[2*k+1]);
    }

    P ar[16], ai[16];
    ar[0] = mul2(t3r[0], cq[3]); ai[0] = K_ZERO;
    ar[1] = mul2(t3r[0], urq[3]); ai[1] = mul2(t3r[0], uiq[3]);
#pragma unroll
    for (int k = 1; k < 8; k++) {
        ar[2*k] = mul2(t3r[k], cq[3]);
        ai[2*k] = mul2(t3i[k], cq[3]);
        cmul(t3r[k], t3i[k], urq[3], uiq[3], ar[2*k+1], ai[2*k+1]);
    }

    // ---- CNOT chains: register relabelings (wire0 = bit value 8) ----
#define SWAMP(p, q) { P t_ = ar[p]; ar[p] = ar[q]; ar[q] = t_; \
                      t_ = ai[p]; ai[p] = ai[q]; ai[q] = t_; }
    SWAMP(8,12) SWAMP(9,13) SWAMP(10,14) SWAMP(11,15)
    SWAMP(4,6)  SWAMP(5,7)  SWAMP(12,14) SWAMP(13,15)
    SWAMP(2,3)  SWAMP(6,7)  SWAMP(10,11) SWAMP(14,15)

    // ---- variational layer: RY then RZ per qubit (batch-packed) ----
    const ulonglong2* trp = (const ulonglong2*)(sw + OFF_TRIG);
#pragma unroll
    for (int i = 0; i < 4; i++) {
        ulonglong2 u0 = trp[i*2], u1 = trp[i*2+1];
        P cy = mkP(u0.x), sy = mkP(u0.y), zc = mkP(u1.x), zs = mkP(u1.y);
        P syn = negP(sy), zsn = negP(zs);
        const int m = 8 >> i;
#pragma unroll
        for (int k = 0; k < 16; k++) {
            if (k & m) continue;
            const int k1 = k | m;
            P a0r = ar[k],  a0i = ai[k];
            P a1r = ar[k1], a1i = ai[k1];
            P n1r = fma2(sy, a0r, mul2(cy, a1r));
            P n1i = fma2(sy, a0i, mul2(cy, a1i));
            ar[k]  = fma2(syn, a1r, mul2(cy, a0r));
            ai[k]  = fma2(syn, a1i, mul2(cy, a0i));
            ar[k1] = fma2(zsn, n1i, mul2(zc, n1r));
            ai[k1] = fma2(zs,  n1r, mul2(zc, n1i));
        }
    }

    // ---- second CNOT chain ----
    SWAMP(8,12) SWAMP(9,13) SWAMP(10,14) SWAMP(11,15)
    SWAMP(4,6)  SWAMP(5,7)  SWAMP(12,14) SWAMP(13,15)
    SWAMP(2,3)  SWAMP(6,7)  SWAMP(10,11) SWAMP(14,15)

    // ---- probs and PauliZ expvals (batch-packed) ----
    P p[16];
#pragma unroll
    for (int k = 0; k < 16; k++) p[k] = fma2(ar[k], ar[k], mul2(ai[k], ai[k]));
    float zA[4], zB[4];
#pragma unroll
    for (int i = 0; i < 4; i++) {
        const int m = 8 >> i;
        P acc = p[0];
#pragma unroll
        for (int k = 1; k < 16; k++)
            acc = (k & m) ? fma2(p[k], K_NEG1, acc) : add2(acc, p[k]);
        unpack2(acc, zA[i], zB[i]);
    }

    // ================= MLP: neuron-pair packing, weight loads shared A/B =================
    const P* B1p = (const P*)(sw + OFF_B1);
    const P* B2p = (const P*)(sw + OFF_B2);
    const P* B3p = (const P*)(sw + OFF_B3);

    // ---- layer 1: 4 -> 16 ----
    P aA1[8], aB1[8];
#pragma unroll
    for (int jp = 0; jp < 8; jp++) { P bb = B1p[jp]; aA1[jp] = bb; aB1[jp] = bb; }
#pragma unroll
    for (int k = 0; k < 4; k++) {
        P dA = dupP(zA[k]), dB = dupP(zB[k]);
        const ulonglong2* row = (const ulonglong2*)(sw + OFF_W1 + k*16);
#pragma unroll
        for (int q = 0; q < 4; q++) {
            ulonglong2 u = row[q];
            P w0 = mkP(u.x), w1 = mkP(u.y);
            aA1[2*q]   = fma2(w0, dA, aA1[2*q]);
            aA1[2*q+1] = fma2(w1, dA, aA1[2*q+1]);
            aB1[2*q]   = fma2(w0, dB, aB1[2*q]);
            aB1[2*q+1] = fma2(w1, dB, aB1[2*q+1]);
        }
    }
    float h1A[16], h1B[16];
#pragma unroll
    for (int jp = 0; jp < 8; jp++) {
        float lo, hi;
        unpack2(aA1[jp], lo, hi);
        h1A[2*jp] = fmaxf(lo, 0.0f); h1A[2*jp+1] = fmaxf(hi, 0.0f);
        unpack2(aB1[jp], lo, hi);
        h1B[2*jp] = fmaxf(lo, 0.0f); h1B[2*jp+1] = fmaxf(hi, 0.0f);
    }

    // ---- layer 2: 16 -> 32 ----
    P aA2[16], aB2[16];
#pragma unroll
    for (int jp = 0; jp < 16; jp++) { P bb = B2p[jp]; aA2[jp] = bb; aB2[jp] = bb; }
#pragma unroll
    for (int k = 0; k < 16; k++) {
        P dA = dupP(h1A[k]), dB = dupP(h1B[k]);
        const ulonglong2* row = (const ulonglong2*)(sw + OFF_W2 + k*32);
#pragma unroll
        for (int q = 0; q < 8; q++) {
            ulonglong2 u = row[q];
            P w0 = mkP(u.x), w1 = mkP(u.y);
            aA2[2*q]   = fma2(w0, dA, aA2[2*q]);
            aA2[2*q+1] = fma2(w1, dA, aA2[2*q+1]);
            aB2[2*q]   = fma2(w0, dB, aB2[2*q]);
            aB2[2*q+1] = fma2(w1, dB, aB2[2*q+1]);
        }
    }
    float h2A[32], h2B[32];
#pragma unroll
    for (int jp = 0; jp < 16; jp++) {
        float lo, hi;
        unpack2(aA2[jp], lo, hi);
        h2A[2*jp] = fmaxf(lo, 0.0f); h2A[2*jp+1] = fmaxf(hi, 0.0f);
        unpack2(aB2[jp], lo, hi);
        h2B[2*jp] = fmaxf(lo, 0.0f); h2B[2*jp+1] = fmaxf(hi, 0.0f);
    }

    // ---- layer 3: 32 -> 16 ----
    P aA3[8], aB3[8];
#pragma unroll
    for (int jp = 0; jp < 8; jp++) { P bb = B3p[jp]; aA3[jp] = bb; aB3[jp] = bb; }
#pragma unroll
    for (int k = 0; k < 32; k++) {
        P dA = dupP(h2A[k]), dB = dupP(h2B[k]);
        const ulonglong2* row = (const ulonglong2*)(sw + OFF_W3 + k*16);
#pragma unroll
        for (int q = 0; q < 4; q++) {
            ulonglong2 u = row[q];
            P w0 = mkP(u.x), w1 = mkP(u.y);
            aA3[2*q]   = fma2(w0, dA, aA3[2*q]);
            aA3[2*q+1] = fma2(w1, dA, aA3[2*q+1]);
            aB3[2*q]   = fma2(w0, dB, aB3[2*q]);
            aB3[2*q+1] = fma2(w1, dB, aB3[2*q+1]);
        }
    }

    // ---- store: acc pairs are already {o_2j, o_2j+1} in memory order ----
    float* o0 = out + (size_t)b0  * 16;
    float* o1 = out + (size_t)b1i * 16;
#pragma unroll
    for (int g = 0; g < 4; g++) {
        float4 v;
        unpack2(aA3[2*g],   v.x, v.y);
        unpack2(aA3[2*g+1], v.z, v.w);
        ((float4*)o0)[g] = v;
        unpack2(aB3[2*g],   v.x, v.y);
        unpack2(aB3[2*g+1], v.z, v.w);
        ((float4*)o1)[g] = v;
    }
}

extern "C" void kernel_launch(void* const* d_in, const int* in_sizes, int n_in,
                              void* d_out, int out_size)
{
    const float* x  = (const float*)d_in[0];
    const float* qw = (const float*)d_in[1];
    const float* W1 = (const float*)d_in[2];
    const float* b1 = (const float*)d_in[3];
    const float* W2 = (const float*)d_in[4];
    const float* b2 = (const float*)d_in[5];
    const float* W3 = (const float*)d_in[6];
    const float* b3 = (const float*)d_in[7];
    float* out = (float*)d_out;

    const int n = in_sizes[0] / 16;           // B (even)
    const int half = n >> 1;
    const int blocks = (half + 255) / 256;
    hqae_kernel<<<blocks, 256>>>(x, qw, W1, b1, W2, b2, W3, b3, out, n);
}